// round 15
// baseline (speedup 1.0000x reference)
#include <cuda_runtime.h>
#include <cuda_bf16.h>

#define BB 4
#define TT 2048
#define HH 12
#define DD 64
#define PP 768
#define NBH (BB*HH)
#define SCALE 0.125f
#define LOG2E 1.4426950408889634f
#define C1 (SCALE * LOG2E)

typedef unsigned long long u64;
typedef unsigned int u32;

// bf16 hi/lo split operands (static device scratch: allowed)
__device__ __nv_bfloat16 g_qh[NBH*TT*DD], g_ql[NBH*TT*DD];
__device__ __nv_bfloat16 g_kh[NBH*TT*DD], g_kl[NBH*TT*DD];
__device__ __nv_bfloat16 g_vh[NBH*DD*TT], g_vl[NBH*DD*TT];   // transposed [bh][d][t]

// ---------------- PTX helpers ----------------
__device__ __forceinline__ u32 smem_u32(const void* p) {
    return (u32)__cvta_generic_to_shared(p);
}
__device__ __forceinline__ void cp_async16(u32 dst, const void* src) {
    asm volatile("cp.async.cg.shared.global [%0], [%1], 16;"
                 :: "r"(dst), "l"(__cvta_generic_to_global(src)));
}
#define CP_COMMIT() asm volatile("cp.async.commit_group;")
#define CP_WAIT0()  asm volatile("cp.async.wait_group 0;")

__device__ __forceinline__ void ldsm4(u32* r, u32 a) {
    asm volatile("ldmatrix.sync.aligned.m8n8.x4.shared.b16 {%0,%1,%2,%3}, [%4];"
        : "=r"(r[0]), "=r"(r[1]), "=r"(r[2]), "=r"(r[3]) : "r"(a));
}
__device__ __forceinline__ void mma_bf16(float* c, const u32* a, const u32* b) {
    asm volatile("mma.sync.aligned.m16n8k16.row.col.f32.bf16.bf16.f32 "
        "{%0,%1,%2,%3}, {%4,%5,%6,%7}, {%8,%9}, {%0,%1,%2,%3};"
        : "+f"(c[0]), "+f"(c[1]), "+f"(c[2]), "+f"(c[3])
        : "r"(a[0]), "r"(a[1]), "r"(a[2]), "r"(a[3]), "r"(b[0]), "r"(b[1]));
}
__device__ __forceinline__ float ex2f(float x) {
    float y; asm("ex2.approx.ftz.f32 %0, %1;" : "=f"(y) : "f"(x)); return y;
}
__device__ __forceinline__ u32 bf16x2(float lo, float hi) {
    u32 r; asm("cvt.rn.bf16x2.f32 %0, %1, %2;" : "=r"(r) : "f"(hi), "f"(lo)); return r;
}
// packed f32x2 (sm_103a, PTX-only)
__device__ __forceinline__ u64 pack2(float lo, float hi) {
    u64 r; asm("mov.b64 %0, {%1, %2};" : "=l"(r) : "f"(lo), "f"(hi)); return r;
}
__device__ __forceinline__ void unpack2(u64 v, float& lo, float& hi) {
    asm("mov.b64 {%0, %1}, %2;" : "=f"(lo), "=f"(hi) : "l"(v));
}
__device__ __forceinline__ void ffma2(u64& d, u64 a, u64 b) {
    asm("fma.rn.f32x2 %0, %1, %2, %0;" : "+l"(d) : "l"(a), "l"(b));
}

// ---------------------------------------------------------------------------
// QKV projection -> bf16 hi/lo splits. f32x2 packed inner loop (qkv is
// fma-pipe bound, acc footprint unchanged: 8 x u64). Coalesced stores (R12).
// ---------------------------------------------------------------------------
__global__ void qkv_kernel(const float* __restrict__ X,
                           const float* __restrict__ Wq, const float* __restrict__ bq,
                           const float* __restrict__ Wk, const float* __restrict__ bk,
                           const float* __restrict__ Wv, const float* __restrict__ bv) {
    __shared__ float Xs[64][65];
    __shared__ float Ws[64][66];     // pitch 66: rows 8B-aligned for LDS.64

    const int which = blockIdx.z;
    const float* W    = (which == 0) ? Wq : (which == 1) ? Wk : Wv;
    const float* bias = (which == 0) ? bq : (which == 1) ? bk : bv;

    const int n0 = blockIdx.x * 64;          // head h = n0>>6
    const int r0 = blockIdx.y * 64;          // token block
    const int tid = threadIdx.x;
    const int tx = tid & 15;
    const int ty = tid >> 4;

    #pragma unroll
    for (int i = 0; i < 4; i++) {
        const int r = i * 16 + ty;
        #pragma unroll
        for (int u = 0; u < 4; u++) {
            const int c = tx * 4 + u;
            Xs[r][c] = X[(r0 + r) * DD + c];
            Ws[r][c] = W[r * PP + n0 + c];
        }
    }
    __syncthreads();

    u64 acc2[4][2] = {};                     // packed along jj pairs
    #pragma unroll 8
    for (int k = 0; k < 64; k++) {
        const u64 b0 = *(const u64*)&Ws[k][tx * 4];
        const u64 b1 = *(const u64*)&Ws[k][tx * 4 + 2];
        #pragma unroll
        for (int ii = 0; ii < 4; ii++) {
            const float a = Xs[ty * 4 + ii][k];
            const u64 a2 = pack2(a, a);
            ffma2(acc2[ii][0], a2, b0);
            ffma2(acc2[ii][1], a2, b1);
        }
    }

    float acc[4][4];
    #pragma unroll
    for (int ii = 0; ii < 4; ii++) {
        unpack2(acc2[ii][0], acc[ii][0], acc[ii][1]);
        unpack2(acc2[ii][1], acc[ii][2], acc[ii][3]);
    }

    const int b_  = r0 >> 11;
    const int h_  = n0 >> 6;
    const int bh  = b_ * HH + h_;
    const int tb  = r0 & (TT - 1);

    if (which == 2) {
        // ---- V: stage transposed [d_local][t_local] in Xs, coalesced write ----
        __syncthreads();
        #pragma unroll
        for (int ii = 0; ii < 4; ii++)
            #pragma unroll
            for (int jj = 0; jj < 4; jj++)
                Xs[tx * 4 + jj][ty * 4 + ii] = acc[ii][jj] + bias[n0 + tx * 4 + jj];
        __syncthreads();

        const int d  = tid >> 2;             // 0..63
        const int t0 = (tid & 3) * 16;       // 16 t-values per thread
        union { __nv_bfloat16 h[16]; uint4 q[2]; } Uh, Ul;
        #pragma unroll
        for (int u = 0; u < 16; u++) {
            const float v = Xs[d][t0 + u];
            const __nv_bfloat16 hi = __float2bfloat16(v);
            Uh.h[u] = hi;
            Ul.h[u] = __float2bfloat16(v - __bfloat162float(hi));
        }
        const size_t base = ((size_t)bh * DD + d) * TT + tb + t0;
        *(uint4*)&g_vh[base]     = Uh.q[0];
        *(uint4*)&g_vh[base + 8] = Uh.q[1];
        *(uint4*)&g_vl[base]     = Ul.q[0];
        *(uint4*)&g_vl[base + 8] = Ul.q[1];
    } else {
        // ---- Q/K: packed 4xbf16 (8B) coalesced stores ----
        __nv_bfloat16* gh = (which == 0) ? g_qh : g_kh;
        __nv_bfloat16* gl = (which == 0) ? g_ql : g_kl;
        #pragma unroll
        for (int ii = 0; ii < 4; ii++) {
            const int t_ = tb + ty * 4 + ii;
            union { __nv_bfloat16 h[4]; u64 q; } Uh, Ul;
            #pragma unroll
            for (int jj = 0; jj < 4; jj++) {
                const float v = acc[ii][jj] + bias[n0 + tx * 4 + jj];
                const __nv_bfloat16 hi = __float2bfloat16(v);
                Uh.h[jj] = hi;
                Ul.h[jj] = __float2bfloat16(v - __bfloat162float(hi));
            }
            const size_t idx = ((size_t)bh * TT + t_) * DD + tx * 4;
            *(u64*)&gh[idx] = Uh.q;
            *(u64*)&gl[idx] = Ul.q;
        }
    }
}

// ---------------------------------------------------------------------------
// HMMA flash attention. 128 thr (4 warps), q-tile 64, k-tile 64, 32 iters,
// 2 CTAs/SM. Single __syncthreads per iter; full mask table preloaded in smem.
// Loop: CP_WAIT0 -> sync -> issue prefetch(next) -> compute(cur).
// ---------------------------------------------------------------------------
#define PITCHB 144                       // bytes per smem row
#define TILEB  (64 * PITCHB)             // 9216 B per 64x64 bf16 tile
#define OFF_QH 0
#define OFF_QL TILEB
#define OFF_KV (2 * TILEB)               // 2 buffers x {KH,KL,VH,VL}
#define BUFSTR (4 * TILEB)
#define OFF_CJ (OFF_KV + 2 * BUFSTR)     // 2048 floats (full mask table)
#define SMEM_TOTAL (OFF_CJ + 2048 * 4)

__global__ __launch_bounds__(128, 2)
void attn_kernel(const float* __restrict__ amask, float* __restrict__ out) {
    extern __shared__ char smem[];
    const u32 sb = smem_u32(smem);
    float* cjs = (float*)(smem + OFF_CJ);  // 2048 entries: all k positions

    const int tid  = threadIdx.x;
    const int wid  = tid >> 5;
    const int lane = tid & 31;
    const int g    = lane >> 2;          // row-in-half group
    const int t4   = lane & 3;           // col pair selector

    const int bh = blockIdx.y;
    const int b_ = bh / HH;
    const int h_ = bh % HH;
    const int q0 = blockIdx.x * 64;
    const int qrow0 = wid * 16;

    const u32 a_lane = (u32)((lane & 15) * PITCHB + (lane >> 4) * 16);          // A-frag
    const u32 b_lane = (u32)((((lane >> 4) & 1) * 8 + (lane & 7)) * PITCHB
                             + ((lane >> 3) & 1) * 16);                          // B-frag pair

    // ---- prologue: Q hi/lo + K/V iter0 via cp.async; mask table via LDG ----
    #pragma unroll
    for (int i = 0; i < 8; i++) {
        const int idx = i * 128 + tid;            // 0..1023
        const int tile = idx >> 9;                // 0:QH 1:QL
        const int w = idx & 511;
        const int row = w >> 3, ch = w & 7;
        cp_async16(sb + tile * TILEB + row * PITCHB + ch * 16,
                   (tile ? g_ql : g_qh) + ((size_t)bh * TT + q0 + row) * DD + ch * 8);
    }
    #pragma unroll
    for (int i = 0; i < 16; i++) {
        const int idx = i * 128 + tid;            // 0..2047
        const int tile = idx >> 9;                // 0:KH 1:KL 2:VH 3:VL
        const int w = idx & 511;
        const int row = w >> 3, ch = w & 7;
        const u32 dst = sb + OFF_KV + tile * TILEB + row * PITCHB + ch * 16;
        const __nv_bfloat16* src;
        if (tile < 2) src = (tile ? g_kl : g_kh) + ((size_t)bh * TT + row) * DD + ch * 8;
        else          src = (tile == 2 ? g_vh : g_vl) + ((size_t)bh * DD + row) * TT + ch * 8;
        cp_async16(dst, src);
    }
    CP_COMMIT();
    #pragma unroll
    for (int i = 0; i < 16; i++) {
        const int j = i * 128 + tid;              // 0..2047
        cjs[j] = (1.0f - amask[b_ * TT + j]) * (-10000.0f * LOG2E);
    }

    u32 qh_fr[4][4], ql_fr[4][4];        // Q A-fragments, resident all kernel
    float o_fr[8][4] = {};               // O accumulators [d-tile][4]
    float psum0 = 0.f, psum1 = 0.f;      // row sums (rows g, g+8)

    for (int it = 0; it < 32; it++) {
        const u32 buf = sb + OFF_KV + (u32)(it & 1) * BUFSTR;

        CP_WAIT0();                      // cur buffer's group (issued last iter) done
        __syncthreads();                 // visibility of all threads' copies + cjs;
                                         // also: everyone finished reading next buf
        if (it == 0) {
            #pragma unroll
            for (int ks = 0; ks < 4; ks++) {
                ldsm4(qh_fr[ks], sb + OFF_QH + (u32)(qrow0 * PITCHB + ks * 32) + a_lane);
                ldsm4(ql_fr[ks], sb + OFF_QL + (u32)(qrow0 * PITCHB + ks * 32) + a_lane);
            }
        }
        if (it < 31) {
            const int k0n = (it + 1) * 64;
            const u32 nbuf = sb + OFF_KV + (u32)((it + 1) & 1) * BUFSTR;
            #pragma unroll
            for (int i = 0; i < 16; i++) {
                const int idx = i * 128 + tid;
                const int tile = idx >> 9;
                const int w = idx & 511;
                const int row = w >> 3, ch = w & 7;
                const u32 dst = nbuf + tile * TILEB + row * PITCHB + ch * 16;
                const __nv_bfloat16* src;
                if (tile < 2) src = (tile ? g_kl : g_kh) + ((size_t)bh * TT + k0n + row) * DD + ch * 8;
                else          src = (tile == 2 ? g_vh : g_vl) + ((size_t)bh * DD + row) * TT + k0n + ch * 8;
                cp_async16(dst, src);
            }
            CP_COMMIT();
        }

        // ---- S = Q K^T (bf16 x3 split), 8 n-tiles of 8 cols ----
        float s_fr[8][4] = {};
        #pragma unroll
        for (int ks = 0; ks < 4; ks++) {
            #pragma unroll
            for (int pt = 0; pt < 4; pt++) {
                const u32 po = (u32)(pt * 16 * PITCHB + ks * 32) + b_lane;
                u32 bh4[4], bl4[4];
                ldsm4(bh4, buf + 0 * TILEB + po);          // KH
                ldsm4(bl4, buf + 1 * TILEB + po);          // KL
                mma_bf16(s_fr[2*pt],   qh_fr[ks], bh4);
                mma_bf16(s_fr[2*pt+1], qh_fr[ks], bh4 + 2);
                mma_bf16(s_fr[2*pt],   ql_fr[ks], bh4);
                mma_bf16(s_fr[2*pt+1], ql_fr[ks], bh4 + 2);
                mma_bf16(s_fr[2*pt],   qh_fr[ks], bl4);
                mma_bf16(s_fr[2*pt+1], qh_fr[ks], bl4 + 2);
            }
        }

        // ---- fixed-base softmax + C->A fragment permutation (no smem) ----
        const float2* cj2 = (const float2*)(cjs + it * 64);
        u32 pa_h[4][4], pa_l[4][4];      // P A-fragments [j-kstep][4]
        #pragma unroll
        for (int jt = 0; jt < 8; jt++) {
            const float2 mk = cj2[4 * jt + t4];
            const float p0 = ex2f(fmaf(s_fr[jt][0], C1, mk.x));
            const float p1 = ex2f(fmaf(s_fr[jt][1], C1, mk.y));
            const float p2 = ex2f(fmaf(s_fr[jt][2], C1, mk.x));
            const float p3 = ex2f(fmaf(s_fr[jt][3], C1, mk.y));
            psum0 += p0 + p1;
            psum1 += p2 + p3;
            const u32 h01 = bf16x2(p0, p1);
            const u32 h23 = bf16x2(p2, p3);
            const float r0 = __uint_as_float(h01 << 16);
            const float r1 = __uint_as_float(h01 & 0xffff0000u);
            const float r2 = __uint_as_float(h23 << 16);
            const float r3 = __uint_as_float(h23 & 0xffff0000u);
            const int m = jt >> 1, sl = (jt & 1) * 2;
            pa_h[m][sl]     = h01;
            pa_h[m][sl + 1] = h23;
            pa_l[m][sl]     = bf16x2(p0 - r0, p1 - r1);
            pa_l[m][sl + 1] = bf16x2(p2 - r2, p3 - r3);
        }

        // ---- O += P V (bf16 x3 split), Vt[d][t]: n-tiles over d ----
        #pragma unroll
        for (int ks = 0; ks < 4; ks++) {
            #pragma unroll
            for (int pt = 0; pt < 4; pt++) {
                const u32 po = (u32)(pt * 16 * PITCHB + ks * 32) + b_lane;
                u32 bh4[4], bl4[4];
                ldsm4(bh4, buf + 2 * TILEB + po);          // VH
                ldsm4(bl4, buf + 3 * TILEB + po);          // VL
                mma_bf16(o_fr[2*pt],   pa_h[ks], bh4);
                mma_bf16(o_fr[2*pt+1], pa_h[ks], bh4 + 2);
                mma_bf16(o_fr[2*pt],   pa_l[ks], bh4);
                mma_bf16(o_fr[2*pt+1], pa_l[ks], bh4 + 2);
                mma_bf16(o_fr[2*pt],   pa_h[ks], bl4);
                mma_bf16(o_fr[2*pt+1], pa_h[ks], bl4 + 2);
            }
        }
    }

    // ---- epilogue: reduce row sums over quad lanes, normalize, store ----
    psum0 += __shfl_xor_sync(0xffffffffu, psum0, 1);
    psum0 += __shfl_xor_sync(0xffffffffu, psum0, 2);
    psum1 += __shfl_xor_sync(0xffffffffu, psum1, 1);
    psum1 += __shfl_xor_sync(0xffffffffu, psum1, 2);
    const float inv0 = 1.0f / psum0;
    const float inv1 = 1.0f / psum1;

    float* orow0 = out + ((size_t)b_ * TT + q0 + qrow0 + g) * PP + h_ * 64;
    float* orow1 = orow0 + (size_t)8 * PP;
    #pragma unroll
    for (int dt = 0; dt < 8; dt++) {
        const int d = 8 * dt + 2 * t4;
        float2 v0 = make_float2(o_fr[dt][0] * inv0, o_fr[dt][1] * inv0);
        float2 v1 = make_float2(o_fr[dt][2] * inv1, o_fr[dt][3] * inv1);
        *(float2*)(orow0 + d) = v0;
        *(float2*)(orow1 + d) = v1;
    }
}

extern "C" void kernel_launch(void* const* d_in, const int* in_sizes, int n_in,
                              void* d_out, int out_size) {
    const float* X    = (const float*)d_in[0];
    const float* mask = (const float*)d_in[1];
    const float* Wq   = (const float*)d_in[2];
    const float* bq   = (const float*)d_in[3];
    const float* Wk   = (const float*)d_in[4];
    const float* bk   = (const float*)d_in[5];
    const float* Wv   = (const float*)d_in[6];
    const float* bv   = (const float*)d_in[7];
    float* out = (float*)d_out;

    dim3 g1(PP / 64, (BB * TT) / 64, 3);
    qkv_kernel<<<g1, 256>>>(X, Wq, bq, Wk, bk, Wv, bv);

    cudaFuncSetAttribute(attn_kernel, cudaFuncAttributeMaxDynamicSharedMemorySize, SMEM_TOTAL);
    attn_kernel<<<dim3(TT / 64, NBH), 128, SMEM_TOTAL>>>(mask, out);
}

// round 16
// speedup vs baseline: 1.4754x; 1.4754x over previous
#include <cuda_runtime.h>
#include <cuda_bf16.h>

#define BB 4
#define TT 2048
#define HH 12
#define DD 64
#define PP 768
#define NBH (BB*HH)
#define SCALE 0.125f
#define LOG2E 1.4426950408889634f
#define C1 (SCALE * LOG2E)

typedef unsigned long long u64;
typedef unsigned int u32;

// bf16 hi/lo split operands (static device scratch: allowed)
__device__ __nv_bfloat16 g_qh[NBH*TT*DD], g_ql[NBH*TT*DD];
__device__ __nv_bfloat16 g_kh[NBH*TT*DD], g_kl[NBH*TT*DD];
__device__ __nv_bfloat16 g_vh[NBH*DD*TT], g_vl[NBH*DD*TT];   // transposed [bh][d][t]

// ---------------- PTX helpers ----------------
__device__ __forceinline__ u32 smem_u32(const void* p) {
    return (u32)__cvta_generic_to_shared(p);
}
__device__ __forceinline__ void cp_async16(u32 dst, const void* src) {
    asm volatile("cp.async.cg.shared.global [%0], [%1], 16;"
                 :: "r"(dst), "l"(__cvta_generic_to_global(src)));
}
#define CP_COMMIT() asm volatile("cp.async.commit_group;")
#define CP_WAIT0()  asm volatile("cp.async.wait_group 0;")

__device__ __forceinline__ void ldsm4(u32* r, u32 a) {
    asm volatile("ldmatrix.sync.aligned.m8n8.x4.shared.b16 {%0,%1,%2,%3}, [%4];"
        : "=r"(r[0]), "=r"(r[1]), "=r"(r[2]), "=r"(r[3]) : "r"(a));
}
__device__ __forceinline__ void mma_bf16(float* c, const u32* a, const u32* b) {
    asm volatile("mma.sync.aligned.m16n8k16.row.col.f32.bf16.bf16.f32 "
        "{%0,%1,%2,%3}, {%4,%5,%6,%7}, {%8,%9}, {%0,%1,%2,%3};"
        : "+f"(c[0]), "+f"(c[1]), "+f"(c[2]), "+f"(c[3])
        : "r"(a[0]), "r"(a[1]), "r"(a[2]), "r"(a[3]), "r"(b[0]), "r"(b[1]));
}
__device__ __forceinline__ float ex2f(float x) {
    float y; asm("ex2.approx.ftz.f32 %0, %1;" : "=f"(y) : "f"(x)); return y;
}
__device__ __forceinline__ u32 bf16x2(float lo, float hi) {
    u32 r; asm("cvt.rn.bf16x2.f32 %0, %1, %2;" : "=r"(r) : "f"(hi), "f"(lo)); return r;
}

// ---------------------------------------------------------------------------
// QKV projection -> bf16 hi/lo splits (R13 known-good: fp32 GEMM core,
// coalesced stores; V staged transposed through smem).
// ---------------------------------------------------------------------------
__global__ void qkv_kernel(const float* __restrict__ X,
                           const float* __restrict__ Wq, const float* __restrict__ bq,
                           const float* __restrict__ Wk, const float* __restrict__ bk,
                           const float* __restrict__ Wv, const float* __restrict__ bv) {
    __shared__ float Xs[64][65];
    __shared__ float Ws[64][65];

    const int which = blockIdx.z;
    const float* W    = (which == 0) ? Wq : (which == 1) ? Wk : Wv;
    const float* bias = (which == 0) ? bq : (which == 1) ? bk : bv;

    const int n0 = blockIdx.x * 64;          // head h = n0>>6
    const int r0 = blockIdx.y * 64;          // token block
    const int tid = threadIdx.x;
    const int tx = tid & 15;
    const int ty = tid >> 4;

    #pragma unroll
    for (int i = 0; i < 4; i++) {
        const int r = i * 16 + ty;
        #pragma unroll
        for (int u = 0; u < 4; u++) {
            const int c = tx * 4 + u;
            Xs[r][c] = X[(r0 + r) * DD + c];
            Ws[r][c] = W[r * PP + n0 + c];
        }
    }
    __syncthreads();

    float acc[4][4] = {};
    #pragma unroll 8
    for (int k = 0; k < 64; k++) {
        float a[4], bf[4];
        #pragma unroll
        for (int ii = 0; ii < 4; ii++) a[ii]  = Xs[ty * 4 + ii][k];
        #pragma unroll
        for (int jj = 0; jj < 4; jj++) bf[jj] = Ws[k][tx * 4 + jj];
        #pragma unroll
        for (int ii = 0; ii < 4; ii++)
            #pragma unroll
            for (int jj = 0; jj < 4; jj++)
                acc[ii][jj] = fmaf(a[ii], bf[jj], acc[ii][jj]);
    }

    const int b_  = r0 >> 11;
    const int h_  = n0 >> 6;
    const int bh  = b_ * HH + h_;
    const int tb  = r0 & (TT - 1);

    if (which == 2) {
        // ---- V: stage transposed [d_local][t_local] in Xs, coalesced write ----
        __syncthreads();
        #pragma unroll
        for (int ii = 0; ii < 4; ii++)
            #pragma unroll
            for (int jj = 0; jj < 4; jj++)
                Xs[tx * 4 + jj][ty * 4 + ii] = acc[ii][jj] + bias[n0 + tx * 4 + jj];
        __syncthreads();

        const int d  = tid >> 2;             // 0..63
        const int t0 = (tid & 3) * 16;       // 16 t-values per thread
        union { __nv_bfloat16 h[16]; uint4 q[2]; } Uh, Ul;
        #pragma unroll
        for (int u = 0; u < 16; u++) {
            const float v = Xs[d][t0 + u];
            const __nv_bfloat16 hi = __float2bfloat16(v);
            Uh.h[u] = hi;
            Ul.h[u] = __float2bfloat16(v - __bfloat162float(hi));
        }
        const size_t base = ((size_t)bh * DD + d) * TT + tb + t0;
        *(uint4*)&g_vh[base]     = Uh.q[0];
        *(uint4*)&g_vh[base + 8] = Uh.q[1];
        *(uint4*)&g_vl[base]     = Ul.q[0];
        *(uint4*)&g_vl[base + 8] = Ul.q[1];
    } else {
        // ---- Q/K: packed 4xbf16 (8B) coalesced stores ----
        __nv_bfloat16* gh = (which == 0) ? g_qh : g_kh;
        __nv_bfloat16* gl = (which == 0) ? g_ql : g_kl;
        #pragma unroll
        for (int ii = 0; ii < 4; ii++) {
            const int t_ = tb + ty * 4 + ii;
            union { __nv_bfloat16 h[4]; u64 q; } Uh, Ul;
            #pragma unroll
            for (int jj = 0; jj < 4; jj++) {
                const float v = acc[ii][jj] + bias[n0 + tx * 4 + jj];
                const __nv_bfloat16 hi = __float2bfloat16(v);
                Uh.h[jj] = hi;
                Ul.h[jj] = __float2bfloat16(v - __bfloat162float(hi));
            }
            const size_t idx = ((size_t)bh * TT + t_) * DD + tx * 4;
            *(u64*)&gh[idx] = Uh.q;
            *(u64*)&gl[idx] = Ul.q;
        }
    }
}

// ---------------------------------------------------------------------------
// HMMA flash attention, PV delayed one k-tile (software pipeline).
// Per iter: [wait+sync] -> S(it) MMAs + PV(it-1) MMAs (48 MMAs queued)
//           -> [sync] -> prefetch(it+1) -> softmax(it) overlapping tensor drain.
// 128 thr (4 warps), q-tile 64, k-tile 64, 32 iters, 2 CTAs/SM.
// ---------------------------------------------------------------------------
#define PITCHB 144                       // bytes per smem row
#define TILEB  (64 * PITCHB)             // 9216 B per 64x64 bf16 tile
#define OFF_QH 0
#define OFF_QL TILEB
#define OFF_KV (2 * TILEB)               // 2 buffers x {KH,KL,VH,VL}
#define BUFSTR (4 * TILEB)
#define OFF_CJ (OFF_KV + 2 * BUFSTR)     // 2048 floats (full mask table)
#define SMEM_TOTAL (OFF_CJ + 2048 * 4)

__global__ __launch_bounds__(128, 2)
void attn_kernel(const float* __restrict__ amask, float* __restrict__ out) {
    extern __shared__ char smem[];
    const u32 sb = smem_u32(smem);
    float* cjs = (float*)(smem + OFF_CJ);  // 2048 entries: all k positions

    const int tid  = threadIdx.x;
    const int wid  = tid >> 5;
    const int lane = tid & 31;
    const int g    = lane >> 2;          // row-in-half group
    const int t4   = lane & 3;           // col pair selector

    const int bh = blockIdx.y;
    const int b_ = bh / HH;
    const int h_ = bh % HH;
    const int q0 = blockIdx.x * 64;
    const int qrow0 = wid * 16;

    const u32 a_lane = (u32)((lane & 15) * PITCHB + (lane >> 4) * 16);          // A-frag
    const u32 b_lane = (u32)((((lane >> 4) & 1) * 8 + (lane & 7)) * PITCHB
                             + ((lane >> 3) & 1) * 16);                          // B-frag pair

    // ---- prologue: Q hi/lo + K/V iter0 via cp.async; full mask table ----
    #pragma unroll
    for (int i = 0; i < 8; i++) {
        const int idx = i * 128 + tid;            // 0..1023
        const int tile = idx >> 9;                // 0:QH 1:QL
        const int w = idx & 511;
        const int row = w >> 3, ch = w & 7;
        cp_async16(sb + tile * TILEB + row * PITCHB + ch * 16,
                   (tile ? g_ql : g_qh) + ((size_t)bh * TT + q0 + row) * DD + ch * 8);
    }
    #pragma unroll
    for (int i = 0; i < 16; i++) {
        const int idx = i * 128 + tid;            // 0..2047
        const int tile = idx >> 9;                // 0:KH 1:KL 2:VH 3:VL
        const int w = idx & 511;
        const int row = w >> 3, ch = w & 7;
        const u32 dst = sb + OFF_KV + tile * TILEB + row * PITCHB + ch * 16;
        const __nv_bfloat16* src;
        if (tile < 2) src = (tile ? g_kl : g_kh) + ((size_t)bh * TT + row) * DD + ch * 8;
        else          src = (tile == 2 ? g_vh : g_vl) + ((size_t)bh * DD + row) * TT + ch * 8;
        cp_async16(dst, src);
    }
    CP_COMMIT();
    #pragma unroll
    for (int i = 0; i < 16; i++) {
        const int j = i * 128 + tid;              // 0..2047
        cjs[j] = (1.0f - amask[b_ * TT + j]) * (-10000.0f * LOG2E);
    }

    u32 qh_fr[4][4], ql_fr[4][4];        // Q A-fragments, resident all kernel
    float o_fr[8][4] = {};               // O accumulators [d-tile][4]
    u32 pa_h[4][4], pa_l[4][4];          // P A-fragments from previous iter
    float psum0 = 0.f, psum1 = 0.f;      // row sums (rows g, g+8)

    for (int it = 0; it < 32; it++) {
        const u32 buf  = sb + OFF_KV + (u32)(it & 1) * BUFSTR;        // K/V(it)
        const u32 obuf = sb + OFF_KV + (u32)((it & 1) ^ 1) * BUFSTR;  // K/V(it-1)

        CP_WAIT0();                      // K/V(it) resident (committed last iter)
        __syncthreads();                 // A: visibility; all warps ready

        if (it == 0) {
            #pragma unroll
            for (int ks = 0; ks < 4; ks++) {
                ldsm4(qh_fr[ks], sb + OFF_QH + (u32)(qrow0 * PITCHB + ks * 32) + a_lane);
                ldsm4(ql_fr[ks], sb + OFF_QL + (u32)(qrow0 * PITCHB + ks * 32) + a_lane);
            }
        }

        // ---- S(it) = Q K^T (bf16 x3 split) ----
        float s_fr[8][4] = {};
        #pragma unroll
        for (int ks = 0; ks < 4; ks++) {
            #pragma unroll
            for (int pt = 0; pt < 4; pt++) {
                const u32 po = (u32)(pt * 16 * PITCHB + ks * 32) + b_lane;
                u32 bh4[4], bl4[4];
                ldsm4(bh4, buf + 0 * TILEB + po);          // KH
                ldsm4(bl4, buf + 1 * TILEB + po);          // KL
                mma_bf16(s_fr[2*pt],   qh_fr[ks], bh4);
                mma_bf16(s_fr[2*pt+1], qh_fr[ks], bh4 + 2);
                mma_bf16(s_fr[2*pt],   ql_fr[ks], bh4);
                mma_bf16(s_fr[2*pt+1], ql_fr[ks], bh4 + 2);
                mma_bf16(s_fr[2*pt],   qh_fr[ks], bl4);
                mma_bf16(s_fr[2*pt+1], qh_fr[ks], bl4 + 2);
            }
        }

        // ---- PV(it-1): O += P V from previous tile (tensor work queued
        //      behind S; drains while softmax below computes) ----
        if (it > 0) {
            #pragma unroll
            for (int ks = 0; ks < 4; ks++) {
                #pragma unroll
                for (int pt = 0; pt < 4; pt++) {
                    const u32 po = (u32)(pt * 16 * PITCHB + ks * 32) + b_lane;
                    u32 bh4[4], bl4[4];
                    ldsm4(bh4, obuf + 2 * TILEB + po);     // VH(it-1)
                    ldsm4(bl4, obuf + 3 * TILEB + po);     // VL(it-1)
                    mma_bf16(o_fr[2*pt],   pa_h[ks], bh4);
                    mma_bf16(o_fr[2*pt+1], pa_h[ks], bh4 + 2);
                    mma_bf16(o_fr[2*pt],   pa_l[ks], bh4);
                    mma_bf16(o_fr[2*pt+1], pa_l[ks], bh4 + 2);
                    mma_bf16(o_fr[2*pt],   pa_h[ks], bl4);
                    mma_bf16(o_fr[2*pt+1], pa_h[ks], bl4 + 2);
                }
            }
        }

        __syncthreads();                 // B: all warps done reading obuf

        if (it < 31) {                   // prefetch K/V(it+1) into obuf slot
            const int k0n = (it + 1) * 64;
            #pragma unroll
            for (int i = 0; i < 16; i++) {
                const int idx = i * 128 + tid;
                const int tile = idx >> 9;
                const int w = idx & 511;
                const int row = w >> 3, ch = w & 7;
                const u32 dst = obuf + tile * TILEB + row * PITCHB + ch * 16;
                const __nv_bfloat16* src;
                if (tile < 2) src = (tile ? g_kl : g_kh) + ((size_t)bh * TT + k0n + row) * DD + ch * 8;
                else          src = (tile == 2 ? g_vh : g_vl) + ((size_t)bh * DD + row) * TT + k0n + ch * 8;
                cp_async16(dst, src);
            }
            CP_COMMIT();
        }

        // ---- softmax(it) -> P frags for next iter's PV (overlaps tensor drain) ----
        const float2* cj2 = (const float2*)(cjs + it * 64);
        #pragma unroll
        for (int jt = 0; jt < 8; jt++) {
            const float2 mk = cj2[4 * jt + t4];
            const float p0 = ex2f(fmaf(s_fr[jt][0], C1, mk.x));
            const float p1 = ex2f(fmaf(s_fr[jt][1], C1, mk.y));
            const float p2 = ex2f(fmaf(s_fr[jt][2], C1, mk.x));
            const float p3 = ex2f(fmaf(s_fr[jt][3], C1, mk.y));
            psum0 += p0 + p1;
            psum1 += p2 + p3;
            const u32 h01 = bf16x2(p0, p1);
            const u32 h23 = bf16x2(p2, p3);
            const float r0 = __uint_as_float(h01 << 16);
            const float r1 = __uint_as_float(h01 & 0xffff0000u);
            const float r2 = __uint_as_float(h23 << 16);
            const float r3 = __uint_as_float(h23 & 0xffff0000u);
            const int m = jt >> 1, sl = (jt & 1) * 2;
            pa_h[m][sl]     = h01;
            pa_h[m][sl + 1] = h23;
            pa_l[m][sl]     = bf16x2(p0 - r0, p1 - r1);
            pa_l[m][sl + 1] = bf16x2(p2 - r2, p3 - r3);
        }
    }

    // ---- final PV(31): buffer (31&1)=1 still intact (no prefetch at it=31) ----
    {
        const u32 lbuf = sb + OFF_KV + 1u * BUFSTR;
        #pragma unroll
        for (int ks = 0; ks < 4; ks++) {
            #pragma unroll
            for (int pt = 0; pt < 4; pt++) {
                const u32 po = (u32)(pt * 16 * PITCHB + ks * 32) + b_lane;
                u32 bh4[4], bl4[4];
                ldsm4(bh4, lbuf + 2 * TILEB + po);         // VH(31)
                ldsm4(bl4, lbuf + 3 * TILEB + po);         // VL(31)
                mma_bf16(o_fr[2*pt],   pa_h[ks], bh4);
                mma_bf16(o_fr[2*pt+1], pa_h[ks], bh4 + 2);
                mma_bf16(o_fr[2*pt],   pa_l[ks], bh4);
                mma_bf16(o_fr[2*pt+1], pa_l[ks], bh4 + 2);
                mma_bf16(o_fr[2*pt],   pa_h[ks], bl4);
                mma_bf16(o_fr[2*pt+1], pa_h[ks], bl4 + 2);
            }
        }
    }

    // ---- epilogue: reduce row sums over quad lanes, normalize, store ----
    psum0 += __shfl_xor_sync(0xffffffffu, psum0, 1);
    psum0 += __shfl_xor_sync(0xffffffffu, psum0, 2);
    psum1 += __shfl_xor_sync(0xffffffffu, psum1, 1);
    psum1 += __shfl_xor_sync(0xffffffffu, psum1, 2);
    const float inv0 = 1.0f / psum0;
    const float inv1 = 1.0f / psum1;

    float* orow0 = out + ((size_t)b_ * TT + q0 + qrow0 + g) * PP + h_ * 64;
    float* orow1 = orow0 + (size_t)8 * PP;
    #pragma unroll
    for (int dt = 0; dt < 8; dt++) {
        const int d = 8 * dt + 2 * t4;
        float2 v0 = make_float2(o_fr[dt][0] * inv0, o_fr[dt][1] * inv0);
        float2 v1 = make_float2(o_fr[dt][2] * inv1, o_fr[dt][3] * inv1);
        *(float2*)(orow0 + d) = v0;
        *(float2*)(orow1 + d) = v1;
    }
}

extern "C" void kernel_launch(void* const* d_in, const int* in_sizes, int n_in,
                              void* d_out, int out_size) {
    const float* X    = (const float*)d_in[0];
    const float* mask = (const float*)d_in[1];
    const float* Wq   = (const float*)d_in[2];
    const float* bq   = (const float*)d_in[3];
    const float* Wk   = (const float*)d_in[4];
    const float* bk   = (const float*)d_in[5];
    const float* Wv   = (const float*)d_in[6];
    const float* bv   = (const float*)d_in[7];
    float* out = (float*)d_out;

    dim3 g1(PP / 64, (BB * TT) / 64, 3);
    qkv_kernel<<<g1, 256>>>(X, Wq, bq, Wk, bk, Wv, bv);

    cudaFuncSetAttribute(attn_kernel, cudaFuncAttributeMaxDynamicSharedMemorySize, SMEM_TOTAL);
    attn_kernel<<<dim3(TT / 64, NBH), 128, SMEM_TOTAL>>>(mask, out);
}

// round 17
// speedup vs baseline: 1.7112x; 1.1598x over previous
#include <cuda_runtime.h>
#include <cuda_bf16.h>

#define BB 4
#define TT 2048
#define HH 12
#define DD 64
#define PP 768
#define NBH (BB*HH)
#define SCALE 0.125f
#define LOG2E 1.4426950408889634f
#define C1 (SCALE * LOG2E)

typedef unsigned long long u64;
typedef unsigned int u32;

// bf16 hi/lo split operands (static device scratch: allowed)
__device__ __nv_bfloat16 g_qh[NBH*TT*DD], g_ql[NBH*TT*DD];
__device__ __nv_bfloat16 g_kh[NBH*TT*DD], g_kl[NBH*TT*DD];
__device__ __nv_bfloat16 g_vh[NBH*DD*TT], g_vl[NBH*DD*TT];   // transposed [bh][d][t]

// ---------------- PTX helpers ----------------
__device__ __forceinline__ u32 smem_u32(const void* p) {
    return (u32)__cvta_generic_to_shared(p);
}
__device__ __forceinline__ void cp_async16(u32 dst, const void* src) {
    asm volatile("cp.async.cg.shared.global [%0], [%1], 16;"
                 :: "r"(dst), "l"(__cvta_generic_to_global(src)));
}
#define CP_COMMIT() asm volatile("cp.async.commit_group;")
#define CP_WAIT1()  asm volatile("cp.async.wait_group 1;")
#define CP_WAIT0()  asm volatile("cp.async.wait_group 0;")

__device__ __forceinline__ void ldsm4(u32* r, u32 a) {
    asm volatile("ldmatrix.sync.aligned.m8n8.x4.shared.b16 {%0,%1,%2,%3}, [%4];"
        : "=r"(r[0]), "=r"(r[1]), "=r"(r[2]), "=r"(r[3]) : "r"(a));
}
__device__ __forceinline__ void mma_bf16(float* c, const u32* a, const u32* b) {
    asm volatile("mma.sync.aligned.m16n8k16.row.col.f32.bf16.bf16.f32 "
        "{%0,%1,%2,%3}, {%4,%5,%6,%7}, {%8,%9}, {%0,%1,%2,%3};"
        : "+f"(c[0]), "+f"(c[1]), "+f"(c[2]), "+f"(c[3])
        : "r"(a[0]), "r"(a[1]), "r"(a[2]), "r"(a[3]), "r"(b[0]), "r"(b[1]));
}
__device__ __forceinline__ float ex2f(float x) {
    float y; asm("ex2.approx.ftz.f32 %0, %1;" : "=f"(y) : "f"(x)); return y;
}
__device__ __forceinline__ u32 bf16x2(float lo, float hi) {
    u32 r; asm("cvt.rn.bf16x2.f32 %0, %1, %2;" : "=r"(r) : "f"(hi), "f"(lo)); return r;
}

#define PITCHB 144                       // bytes per smem row (bf16 tiles)
#define TILEB  (64 * PITCHB)             // 9216 B per 64x64 bf16 tile

// ---------------------------------------------------------------------------
// QKV projection via HMMA bf16x3 split. One 64x64 output tile per block,
// 128 threads (4 warps). X,W tiles converted to hi/lo bf16 in smem; S-phase
// MMA loop identical in structure to attn. Epilogue stages fp32 through smem
// (aliasing the bf16 tiles after a sync) and reuses the proven R12/R13
// coalesced store paths (V transposed to [bh][d][t]).
// ---------------------------------------------------------------------------
__global__ void qkv_kernel(const float* __restrict__ X,
                           const float* __restrict__ Wq, const float* __restrict__ bq,
                           const float* __restrict__ Wk, const float* __restrict__ bk,
                           const float* __restrict__ Wv, const float* __restrict__ bv) {
    __shared__ __align__(16) char qsm[4 * TILEB];    // XH | XL | WH | WL (36864 B)

    const int which = blockIdx.z;
    const float* W    = (which == 0) ? Wq : (which == 1) ? Wk : Wv;
    const float* bias = (which == 0) ? bq : (which == 1) ? bk : bv;

    const int n0 = blockIdx.x * 64;          // output col block (head h = n0>>6)
    const int r0 = blockIdx.y * 64;          // token block
    const int tid  = threadIdx.x;
    const int wid  = tid >> 5;
    const int lane = tid & 31;
    const int g    = lane >> 2;
    const int t4   = lane & 3;

    char* XH = qsm;
    char* XL = qsm + TILEB;
    char* WH = qsm + 2 * TILEB;
    char* WL = qsm + 3 * TILEB;

    // ---- load X tile [64 tok][64 k] -> hi/lo bf16, pitch 144 ----
    #pragma unroll
    for (int p = 0; p < 8; p++) {
        const int idx = p * 128 + tid;        // 0..1023 float4 slots
        const int row = idx >> 4;
        const int c4  = (idx & 15) * 4;
        const float4 xv = *(const float4*)&X[(size_t)(r0 + row) * DD + c4];
        const float f[4] = {xv.x, xv.y, xv.z, xv.w};
        union { __nv_bfloat16 h[4]; u64 q; } Hh, Hl;
        #pragma unroll
        for (int u = 0; u < 4; u++) {
            Hh.h[u] = __float2bfloat16(f[u]);
            Hl.h[u] = __float2bfloat16(f[u] - __bfloat162float(Hh.h[u]));
        }
        *(u64*)(XH + row * PITCHB + c4 * 2) = Hh.q;
        *(u64*)(XL + row * PITCHB + c4 * 2) = Hl.q;
    }
    // ---- load W tile transposed -> Ws[n][k] hi/lo bf16 (coalesced global) ----
    #pragma unroll
    for (int p = 0; p < 8; p++) {
        const int idx = p * 128 + tid;        // 0..1023
        const int k  = idx >> 4;
        const int n4 = (idx & 15) * 4;
        const float4 wv = *(const float4*)&W[(size_t)k * PP + n0 + n4];
        const float f[4] = {wv.x, wv.y, wv.z, wv.w};
        #pragma unroll
        for (int u = 0; u < 4; u++) {
            const __nv_bfloat16 h = __float2bfloat16(f[u]);
            const __nv_bfloat16 l = __float2bfloat16(f[u] - __bfloat162float(h));
            *(__nv_bfloat16*)(WH + (n4 + u) * PITCHB + k * 2) = h;
            *(__nv_bfloat16*)(WL + (n4 + u) * PITCHB + k * 2) = l;
        }
    }
    __syncthreads();

    // ---- HMMA mainloop: out = (Xh+Xl)(Wh+Wl), 3 split terms ----
    const u32 sbq = smem_u32(qsm);
    const u32 a_lane = (u32)((lane & 15) * PITCHB + (lane >> 4) * 16);
    const u32 b_lane = (u32)((((lane >> 4) & 1) * 8 + (lane & 7)) * PITCHB
                             + ((lane >> 3) & 1) * 16);
    const int qrow0 = wid * 16;

    u32 ah[4][4], al[4][4];
    #pragma unroll
    for (int ks = 0; ks < 4; ks++) {
        ldsm4(ah[ks], sbq + 0 * TILEB + (u32)(qrow0 * PITCHB + ks * 32) + a_lane);
        ldsm4(al[ks], sbq + 1 * TILEB + (u32)(qrow0 * PITCHB + ks * 32) + a_lane);
    }
    float c[8][4] = {};
    #pragma unroll
    for (int ks = 0; ks < 4; ks++) {
        #pragma unroll
        for (int pt = 0; pt < 4; pt++) {
            const u32 po = (u32)(pt * 16 * PITCHB + ks * 32) + b_lane;
            u32 bh4[4], bl4[4];
            ldsm4(bh4, sbq + 2 * TILEB + po);
            ldsm4(bl4, sbq + 3 * TILEB + po);
            mma_bf16(c[2*pt],   ah[ks], bh4);
            mma_bf16(c[2*pt+1], ah[ks], bh4 + 2);
            mma_bf16(c[2*pt],   al[ks], bh4);
            mma_bf16(c[2*pt+1], al[ks], bh4 + 2);
            mma_bf16(c[2*pt],   ah[ks], bl4);
            mma_bf16(c[2*pt+1], ah[ks], bl4 + 2);
        }
    }
    __syncthreads();          // all warps done reading bf16 tiles -> alias as f32

    // ---- stage accumulators (+bias) into f32 smem [64][65] ----
    // fragment map: c[j] covers cols n = 8j + 2*t4 + {0,1}; rows qrow0+g / +8.
    float* Ss = (float*)qsm;
    #pragma unroll
    for (int j = 0; j < 8; j++) {
        const int n  = 8 * j + 2 * t4;
        const float b0v = bias[n0 + n];
        const float b1v = bias[n0 + n + 1];
        const int ra = qrow0 + g;
        const int rb = qrow0 + g + 8;
        if (which == 2) {     // V: store transposed [d][t]
            Ss[n * 65 + ra]       = c[j][0] + b0v;
            Ss[(n + 1) * 65 + ra] = c[j][1] + b1v;
            Ss[n * 65 + rb]       = c[j][2] + b0v;
            Ss[(n + 1) * 65 + rb] = c[j][3] + b1v;
        } else {              // Q/K: [t][d]
            Ss[ra * 65 + n]     = c[j][0] + b0v;
            Ss[ra * 65 + n + 1] = c[j][1] + b1v;
            Ss[rb * 65 + n]     = c[j][2] + b0v;
            Ss[rb * 65 + n + 1] = c[j][3] + b1v;
        }
    }
    __syncthreads();

    const int b_  = r0 >> 11;
    const int h_  = n0 >> 6;
    const int bh  = b_ * HH + h_;
    const int tb  = r0 & (TT - 1);

    if (which == 2) {
        // ---- V: coalesced 16B row stores to [bh][d][t] ----
        const int d  = tid >> 1;             // 0..63 (128 threads)
        const int t0 = (tid & 1) * 32;       // 32 t-values per thread
        #pragma unroll
        for (int half = 0; half < 2; half++) {
            union { __nv_bfloat16 h[16]; uint4 q[2]; } Uh, Ul;
            #pragma unroll
            for (int u = 0; u < 16; u++) {
                const float v = Ss[d * 65 + t0 + half * 16 + u];
                const __nv_bfloat16 hi = __float2bfloat16(v);
                Uh.h[u] = hi;
                Ul.h[u] = __float2bfloat16(v - __bfloat162float(hi));
            }
            const size_t base = ((size_t)bh * DD + d) * TT + tb + t0 + half * 16;
            *(uint4*)&g_vh[base]     = Uh.q[0];
            *(uint4*)&g_vh[base + 8] = Uh.q[1];
            *(uint4*)&g_vl[base]     = Ul.q[0];
            *(uint4*)&g_vl[base + 8] = Ul.q[1];
        }
    } else {
        // ---- Q/K: packed 4xbf16 (8B) coalesced stores ----
        __nv_bfloat16* gh = (which == 0) ? g_qh : g_kh;
        __nv_bfloat16* gl = (which == 0) ? g_ql : g_kl;
        const int tx = tid & 15;
        const int ty = tid >> 4;             // 0..7 -> 8 row groups of 8
        #pragma unroll
        for (int ii = 0; ii < 8; ii++) {
            const int row = ty * 8 + ii;
            const int t_  = tb + row;
            union { __nv_bfloat16 h[4]; u64 q; } Uh, Ul;
            #pragma unroll
            for (int jj = 0; jj < 4; jj++) {
                const float v = Ss[row * 65 + tx * 4 + jj];
                const __nv_bfloat16 hi = __float2bfloat16(v);
                Uh.h[jj] = hi;
                Ul.h[jj] = __float2bfloat16(v - __bfloat162float(hi));
            }
            const size_t idx = ((size_t)bh * TT + t_) * DD + tx * 4;
            *(u64*)&gh[idx] = Uh.q;
            *(u64*)&gl[idx] = Ul.q;
        }
    }
}

// ---------------------------------------------------------------------------
// HMMA flash attention (R13 exact: measured 387us). 128 thr (4 warps),
// q-tile 64, k-tile 64, 32 iters, 2 CTAs/SM for phase overlap.
// ---------------------------------------------------------------------------
#define OFF_QH 0
#define OFF_QL TILEB
#define OFF_KV (2 * TILEB)               // 2 buffers x {KH,KL,VH,VL}
#define BUFSTR (4 * TILEB)
#define OFF_CJ (OFF_KV + 2 * BUFSTR)     // 64 floats
#define SMEM_TOTAL (OFF_CJ + 256)

__global__ __launch_bounds__(128, 2)
void attn_kernel(const float* __restrict__ amask, float* __restrict__ out) {
    extern __shared__ char smem[];
    const u32 sb = smem_u32(smem);
    float* cjs = (float*)(smem + OFF_CJ);

    const int tid  = threadIdx.x;
    const int wid  = tid >> 5;
    const int lane = tid & 31;
    const int g    = lane >> 2;
    const int t4   = lane & 3;

    const int bh = blockIdx.y;
    const int b_ = bh / HH;
    const int h_ = bh % HH;
    const int q0 = blockIdx.x * 64;
    const int qrow0 = wid * 16;

    const u32 a_lane = (u32)((lane & 15) * PITCHB + (lane >> 4) * 16);
    const u32 b_lane = (u32)((((lane >> 4) & 1) * 8 + (lane & 7)) * PITCHB
                             + ((lane >> 3) & 1) * 16);

    #pragma unroll
    for (int i = 0; i < 8; i++) {
        const int idx = i * 128 + tid;
        const int tile = idx >> 9;
        const int w = idx & 511;
        const int row = w >> 3, ch = w & 7;
        cp_async16(sb + tile * TILEB + row * PITCHB + ch * 16,
                   (tile ? g_ql : g_qh) + ((size_t)bh * TT + q0 + row) * DD + ch * 8);
    }
    #pragma unroll
    for (int i = 0; i < 16; i++) {
        const int idx = i * 128 + tid;
        const int tile = idx >> 9;
        const int w = idx & 511;
        const int row = w >> 3, ch = w & 7;
        const u32 dst = sb + OFF_KV + tile * TILEB + row * PITCHB + ch * 16;
        const __nv_bfloat16* src;
        if (tile < 2) src = (tile ? g_kl : g_kh) + ((size_t)bh * TT + row) * DD + ch * 8;
        else          src = (tile == 2 ? g_vh : g_vl) + ((size_t)bh * DD + row) * TT + ch * 8;
        cp_async16(dst, src);
    }
    CP_COMMIT();

    u32 qh_fr[4][4], ql_fr[4][4];
    float o_fr[8][4] = {};
    float psum0 = 0.f, psum1 = 0.f;

    for (int it = 0; it < 32; it++) {
        const u32 buf = sb + OFF_KV + (u32)(it & 1) * BUFSTR;

        __syncthreads();
        if (tid < 64)
            cjs[tid] = (1.0f - amask[b_ * TT + it * 64 + tid]) * (-10000.0f * LOG2E);
        if (it < 31) {
            const int k0n = (it + 1) * 64;
            const u32 nbuf = sb + OFF_KV + (u32)((it + 1) & 1) * BUFSTR;
            #pragma unroll
            for (int i = 0; i < 16; i++) {
                const int idx = i * 128 + tid;
                const int tile = idx >> 9;
                const int w = idx & 511;
                const int row = w >> 3, ch = w & 7;
                const u32 dst = nbuf + tile * TILEB + row * PITCHB + ch * 16;
                const __nv_bfloat16* src;
                if (tile < 2) src = (tile ? g_kl : g_kh) + ((size_t)bh * TT + k0n + row) * DD + ch * 8;
                else          src = (tile == 2 ? g_vh : g_vl) + ((size_t)bh * DD + row) * TT + k0n + ch * 8;
                cp_async16(dst, src);
            }
            CP_COMMIT();
            CP_WAIT1();
        } else {
            CP_WAIT0();
        }
        __syncthreads();

        if (it == 0) {
            #pragma unroll
            for (int ks = 0; ks < 4; ks++) {
                ldsm4(qh_fr[ks], sb + OFF_QH + (u32)(qrow0 * PITCHB + ks * 32) + a_lane);
                ldsm4(ql_fr[ks], sb + OFF_QL + (u32)(qrow0 * PITCHB + ks * 32) + a_lane);
            }
        }

        float s_fr[8][4] = {};
        #pragma unroll
        for (int ks = 0; ks < 4; ks++) {
            #pragma unroll
            for (int pt = 0; pt < 4; pt++) {
                const u32 po = (u32)(pt * 16 * PITCHB + ks * 32) + b_lane;
                u32 bh4[4], bl4[4];
                ldsm4(bh4, buf + 0 * TILEB + po);
                ldsm4(bl4, buf + 1 * TILEB + po);
                mma_bf16(s_fr[2*pt],   qh_fr[ks], bh4);
                mma_bf16(s_fr[2*pt+1], qh_fr[ks], bh4 + 2);
                mma_bf16(s_fr[2*pt],   ql_fr[ks], bh4);
                mma_bf16(s_fr[2*pt+1], ql_fr[ks], bh4 + 2);
                mma_bf16(s_fr[2*pt],   qh_fr[ks], bl4);
                mma_bf16(s_fr[2*pt+1], qh_fr[ks], bl4 + 2);
            }
        }

        u32 pa_h[4][4], pa_l[4][4];
        #pragma unroll
        for (int jt = 0; jt < 8; jt++) {
            const float cj0 = cjs[8*jt + 2*t4];
            const float cj1 = cjs[8*jt + 2*t4 + 1];
            const float p0 = ex2f(fmaf(s_fr[jt][0], C1, cj0));
            const float p1 = ex2f(fmaf(s_fr[jt][1], C1, cj1));
            const float p2 = ex2f(fmaf(s_fr[jt][2], C1, cj0));
            const float p3 = ex2f(fmaf(s_fr[jt][3], C1, cj1));
            psum0 += p0 + p1;
            psum1 += p2 + p3;
            const u32 h01 = bf16x2(p0, p1);
            const u32 h23 = bf16x2(p2, p3);
            const float r0 = __uint_as_float(h01 << 16);
            const float r1 = __uint_as_float(h01 & 0xffff0000u);
            const float r2 = __uint_as_float(h23 << 16);
            const float r3 = __uint_as_float(h23 & 0xffff0000u);
            const int m = jt >> 1, sl = (jt & 1) * 2;
            pa_h[m][sl]     = h01;
            pa_h[m][sl + 1] = h23;
            pa_l[m][sl]     = bf16x2(p0 - r0, p1 - r1);
            pa_l[m][sl + 1] = bf16x2(p2 - r2, p3 - r3);
        }

        #pragma unroll
        for (int ks = 0; ks < 4; ks++) {
            #pragma unroll
            for (int pt = 0; pt < 4; pt++) {
                const u32 po = (u32)(pt * 16 * PITCHB + ks * 32) + b_lane;
                u32 bh4[4], bl4[4];
                ldsm4(bh4, buf + 2 * TILEB + po);
                ldsm4(bl4, buf + 3 * TILEB + po);
                mma_bf16(o_fr[2*pt],   pa_h[ks], bh4);
                mma_bf16(o_fr[2*pt+1], pa_h[ks], bh4 + 2);
                mma_bf16(o_fr[2*pt],   pa_l[ks], bh4);
                mma_bf16(o_fr[2*pt+1], pa_l[ks], bh4 + 2);
                mma_bf16(o_fr[2*pt],   pa_h[ks], bl4);
                mma_bf16(o_fr[2*pt+1], pa_h[ks], bl4 + 2);
            }
        }
    }

    psum0 += __shfl_xor_sync(0xffffffffu, psum0, 1);
    psum0 += __shfl_xor_sync(0xffffffffu, psum0, 2);
    psum1 += __shfl_xor_sync(0xffffffffu, psum1, 1);
    psum1 += __shfl_xor_sync(0xffffffffu, psum1, 2);
    const float inv0 = 1.0f / psum0;
    const float inv1 = 1.0f / psum1;

    float* orow0 = out + ((size_t)b_ * TT + q0 + qrow0 + g) * PP + h_ * 64;
    float* orow1 = orow0 + (size_t)8 * PP;
    #pragma unroll
    for (int dt = 0; dt < 8; dt++) {
        const int d = 8 * dt + 2 * t4;
        float2 v0 = make_float2(o_fr[dt][0] * inv0, o_fr[dt][1] * inv0);
        float2 v1 = make_float2(o_fr[dt][2] * inv1, o_fr[dt][3] * inv1);
        *(float2*)(orow0 + d) = v0;
        *(float2*)(orow1 + d) = v1;
    }
}

extern "C" void kernel_launch(void* const* d_in, const int* in_sizes, int n_in,
                              void* d_out, int out_size) {
    const float* X    = (const float*)d_in[0];
    const float* mask = (const float*)d_in[1];
    const float* Wq   = (const float*)d_in[2];
    const float* bq   = (const float*)d_in[3];
    const float* Wk   = (const float*)d_in[4];
    const float* bk   = (const float*)d_in[5];
    const float* Wv   = (const float*)d_in[6];
    const float* bv   = (const float*)d_in[7];
    float* out = (float*)d_out;

    dim3 g1(PP / 64, (BB * TT) / 64, 3);
    qkv_kernel<<<g1, 128>>>(X, Wq, bq, Wk, bk, Wv, bv);

    cudaFuncSetAttribute(attn_kernel, cudaFuncAttributeMaxDynamicSharedMemorySize, SMEM_TOTAL);
    attn_kernel<<<dim3(TT / 64, NBH), 128, SMEM_TOTAL>>>(mask, out);
}